// round 14
// baseline (speedup 1.0000x reference)
#include <cuda_runtime.h>

// ---------------------------------------------------------------------------
// G1_sub2_and_sub3_update
//
// Stage A  (sub2): out[rc[c]] = emb[rc[c]] + sum_{e: col==c} emb[ls[s2row[e]]]
//                               + (n_ent - deg2[c])
// Stage A2: Q[r]  = sum_{j=0..3} out[lc[(r+j) % n_typ]]      (quad-sum table)
// Stage B  (sub3): if node c's 4 edges are rows (r0..r0+3 mod n_typ):
//                      msg = Q[r0] + (n_typ - 4)
//                  out[rs[c]] = emb[rs[c]] * (1 - msg / 5)
//
// The quad-consecutive pattern is VALIDATED per tile (shfl within the edge
// quad + column checks + boundary probes, one __syncthreads_and); exact
// generic fallback otherwise. Q lives in a static __device__ array.
// ---------------------------------------------------------------------------

#define EMB_D    128
#define TILE     64
#define MAX_TYP  4096

__device__ float g_Q[(size_t)MAX_TYP * EMB_D];   // 2 MB static scratch

static __device__ __forceinline__ int lower_bound_i(const int* __restrict__ a, int n, int v) {
    int lo = 0, hi = n;
    while (lo < hi) {
        int m = (lo + hi) >> 1;
        if (__ldg(a + m) < v) lo = m + 1; else hi = m;
    }
    return lo;
}

static __device__ __forceinline__ void seg_bounds(const int* __restrict__ col, int E,
                                                  int c, int degGuess,
                                                  int& lo, int& hi) {
    lo = c * degGuess;
    hi = lo + degGuess;
    bool ok = (hi <= E)
           && (__ldg(col + lo) == c)
           && (__ldg(col + hi - 1) == c)
           && (lo == 0 || __ldg(col + lo - 1) != c)
           && (hi == E || __ldg(col + hi) != c);
    if (!ok) {
        lo = lower_bound_i(col, E, c);
        hi = lower_bound_i(col, E, c + 1);
    }
}

// ---------------- Stage A: one block (512 thr = 4 edge-groups x 128 dims) --
__global__ __launch_bounds__(512)
void k_type_update(const float* __restrict__ emb,
                   const int* __restrict__ s2row,
                   const int* __restrict__ s2col, int E2, int degGuess2,
                   const int* __restrict__ ls,
                   const int* __restrict__ rc,
                   float n_ent_f,
                   float* __restrict__ out) {
    __shared__ float red[512];
    const int c   = blockIdx.x;
    const int tid = threadIdx.x;
    const int d   = tid & 127;     // dim
    const int g   = tid >> 7;      // edge group 0..3

    int lo, hi;
    seg_bounds(s2col, E2, c, degGuess2, lo, hi);
    const int deg = hi - lo;

    float acc = 0.f;
    if (deg == 64) {
        const int base = lo + g * 16;
        int rr[16];
#pragma unroll
        for (int i = 0; i < 16; ++i) rr[i] = __ldg(s2row + base + i);
#pragma unroll
        for (int i = 0; i < 16; ++i) rr[i] = __ldg(ls + rr[i]);
        float v[16];
#pragma unroll
        for (int i = 0; i < 16; ++i) v[i] = __ldg(emb + (size_t)rr[i] * EMB_D + d);
#pragma unroll
        for (int i = 0; i < 16; ++i) acc += v[i];
    } else {
        for (int e = lo + g; e < hi; e += 4) {
            int r = __ldg(s2row + e);
            int s = __ldg(ls + r);
            acc += __ldg(emb + (size_t)s * EMB_D + d);
        }
    }

    red[tid] = acc;
    __syncthreads();
    if (g == 0) {
        float total = red[d] + red[128 + d] + red[256 + d] + red[384 + d];
        const int node = __ldg(rc + c);
        const float base = __ldg(emb + (size_t)node * EMB_D + d);
        out[(size_t)node * EMB_D + d] = base + total + (n_ent_f - (float)deg);
    }
}

// ---------------- Stage A2: build the quad-sum table -----------------------
__global__ __launch_bounds__(128)
void k_build_q(const float* __restrict__ out,
               const int* __restrict__ lc,
               int n_typ) {
    const int r = blockIdx.x;
    const int d = threadIdx.x;
    int r1 = r + 1; if (r1 >= n_typ) r1 -= n_typ;
    int r2 = r + 2; if (r2 >= n_typ) r2 -= n_typ;
    int r3 = r + 3; if (r3 >= n_typ) r3 -= n_typ;
    const int i0 = __ldg(lc + r);
    const int i1 = __ldg(lc + r1);
    const int i2 = __ldg(lc + r2);
    const int i3 = __ldg(lc + r3);
    const float v0 = __ldg(out + (size_t)i0 * EMB_D + d);
    const float v1 = __ldg(out + (size_t)i1 * EMB_D + d);
    const float v2 = __ldg(out + (size_t)i2 * EMB_D + d);
    const float v3 = __ldg(out + (size_t)i3 * EMB_D + d);
    g_Q[(size_t)r * EMB_D + d] = (v0 + v1) + (v2 + v3);
}

// ---------------- Stage B: 64-node tiles, Q-table fast path ----------------
__global__ __launch_bounds__(256)
void k_entity_tiled(const float* __restrict__ emb,
                    const int* __restrict__ s3row,
                    const int* __restrict__ s3col, int E3, int degGuess3,
                    const int* __restrict__ lc,
                    const int* __restrict__ rs,
                    int n_ent, float n_typ_f, int n_typ, int q_ok,
                    float* out) {
    __shared__ __align__(16) int s_r0[TILE];   // base type row per node
    __shared__ __align__(16) int s_rs[TILE];   // output node id per node

    const int t      = threadIdx.x;
    const int c_base = blockIdx.x * TILE;
    const int nloc   = min(TILE, n_ent - c_base);

    const bool tile_full = q_ok && (degGuess3 == 4) && (nloc == TILE)
                        && (4 * (size_t)n_ent <= (size_t)E3);

    bool ok = tile_full;
    if (tile_full) {
        const int e = 4 * c_base + t;               // this tile's 256 edges
        const int r     = __ldg(s3row + e);
        const int col_e = __ldg(s3col + e);
        // Quad base comes from the same warp: lanes (lane & ~3).
        const int lane = t & 31;
        const int rb = __shfl_sync(0xffffffffu, r, lane & ~3);
        int expv = rb + (t & 3);
        if (expv >= n_typ) expv -= n_typ;
        ok = (col_e == (e >> 2)) && (r == expv);
        if ((t & 3) == 0) s_r0[t >> 2] = r;
        if (t < TILE)     s_rs[t] = __ldg(rs + c_base + t);
        if (t == 0) {
            ok = ok && ((c_base == 0) || (__ldg(s3col + 4 * c_base - 1) < c_base));
        } else if (t == 1) {
            const int endi = 4 * (c_base + TILE);
            ok = ok && ((endi >= E3) || (__ldg(s3col + endi) >= c_base + TILE));
        }
    }
    const int allok = __syncthreads_and(ok ? 1 : 0);   // barrier + reduce

    const int w    = t >> 5;
    const int lane = t & 31;

    if (allok) {
        const float bias = n_typ_f - 4.f;
        const float inv  = 0.2f;                        // 1/(1+4)

        // warp w handles local nodes [w*8, w*8+8), four at a time
#pragma unroll
        for (int h = 0; h < 2; ++h) {
            const int m0 = w * 8 + h * 4;
            int r0[4], nd[4];
#pragma unroll
            for (int i = 0; i < 4; ++i) { r0[i] = s_r0[m0 + i]; nd[i] = s_rs[m0 + i]; }
            float4 q[4], ev[4];
#pragma unroll
            for (int i = 0; i < 4; ++i)
                q[i]  = __ldg((const float4*)(g_Q + (size_t)r0[i] * EMB_D) + lane);
#pragma unroll
            for (int i = 0; i < 4; ++i)
                ev[i] = __ldg((const float4*)(emb + (size_t)nd[i] * EMB_D) + lane);
#pragma unroll
            for (int i = 0; i < 4; ++i) {
                float4 res;
                res.x = ev[i].x * (1.f - (q[i].x + bias) * inv);
                res.y = ev[i].y * (1.f - (q[i].y + bias) * inv);
                res.z = ev[i].z * (1.f - (q[i].z + bias) * inv);
                res.w = ev[i].w * (1.f - (q[i].w + bias) * inv);
                *((float4*)(out + (size_t)nd[i] * EMB_D) + lane) = res;
            }
        }
    } else {
        // ---- Generic fallback: warp per node, exact bounds, live gathers ----
        for (int k = 0; k < 8; ++k) {
            const int m = w * 8 + k;
            if (m >= nloc) break;
            const int c = c_base + m;

            int lo, hi;
            seg_bounds(s3col, E3, c, degGuess3, lo, hi);
            const int deg = hi - lo;
            const float inv  = 1.f / (1.f + (float)deg);
            const float bias = n_typ_f - (float)deg;

            const int node = __ldg(rs + c);
            const float4 e4 = __ldg((const float4*)(emb + (size_t)node * EMB_D) + lane);

            float4 msg = make_float4(bias, bias, bias, bias);
            for (int e = lo; e < hi; ++e) {
                const int tt = __ldg(lc + __ldg(s3row + e));
                const float4 v = __ldg((const float4*)(out + (size_t)tt * EMB_D) + lane);
                msg.x += v.x; msg.y += v.y; msg.z += v.z; msg.w += v.w;
            }
            float4 res;
            res.x = e4.x * (1.f - msg.x * inv);
            res.y = e4.y * (1.f - msg.y * inv);
            res.z = e4.z * (1.f - msg.z * inv);
            res.w = e4.w * (1.f - msg.w * inv);
            *((float4*)(out + (size_t)node * EMB_D) + lane) = res;
        }
    }
}

extern "C" void kernel_launch(void* const* d_in, const int* in_sizes, int n_in,
                              void* d_out, int out_size) {
    const float* emb  = (const float*)d_in[0];
    const int* s2row  = (const int*)d_in[1];
    const int* s2col  = (const int*)d_in[2];
    const int* s3row  = (const int*)d_in[3];
    const int* s3col  = (const int*)d_in[4];
    const int* ls     = (const int*)d_in[5];
    const int* rc     = (const int*)d_in[6];
    const int* lc     = (const int*)d_in[7];
    const int* rs     = (const int*)d_in[8];

    const int E2    = in_sizes[1];
    const int E3    = in_sizes[3];
    const int n_ent = in_sizes[5];
    const int n_typ = in_sizes[6];

    const int degGuess2 = (n_typ > 0) ? (E2 / n_typ) : 1;
    const int degGuess3 = (n_ent > 0) ? (E3 / n_ent) : 1;

    float* out = (float*)d_out;

    // Stage A: update type rows into out.
    k_type_update<<<n_typ, 512>>>(emb, s2row, s2col, E2, degGuess2, ls, rc,
                                  (float)n_ent, out);

    // Stage A2: quad-sum table over the updated type rows.
    const int q_ok = (n_typ > 0 && n_typ <= MAX_TYP) ? 1 : 0;
    if (q_ok) {
        k_build_q<<<n_typ, EMB_D>>>(out, lc, n_typ);
    }

    // Stage B: 64-node tiles, Q fast path.
    const int blocks = (n_ent + TILE - 1) / TILE;
    k_entity_tiled<<<blocks, 256>>>(emb, s3row, s3col, E3, degGuess3,
                                    lc, rs, n_ent, (float)n_typ, n_typ, q_ok, out);
}